// round 13
// baseline (speedup 1.0000x reference)
#include <cuda_runtime.h>
#include <math.h>

#define N_NODES    100000
#define N_EDGES    1600000
#define F_IN       100
#define HEADS      3
#define HEAD_DIM   64
#define HIDDEN     192
#define NUM_GRAPHS 128
#define NUM_CLASSES 2
#define NTILE      8
#define N_TILES    (N_NODES / NTILE)   // 12500
#define SCAN_BLK   1024
#define SCAN_NB    ((N_NODES + SCAN_BLK - 1) / SCAN_BLK)   // 98
#define POOL_N     (NUM_GRAPHS * HIDDEN)                   // 24576
#define DEG_BINS   64
#define SORT_BINS  (NUM_GRAPHS * DEG_BINS)                 // 8192
#define GEMM_SMEM_FLOATS (F_IN * HIDDEN + F_IN * NTILE)    // 19200 + 800
#define GEMM_SMEM_BYTES  (GEMM_SMEM_FLOATS * 4)            // 80000

// ---------------- scratch (device globals; no allocations allowed) ----------
__device__ float    g_h[N_NODES * HIDDEN];       // 76.8 MB fp32
__device__ float4   g_as4[N_NODES];              // a_src per node (xyz used)
__device__ float4   g_ad4[N_NODES];              // a_dst per node
__device__ int      g_deg[N_NODES];              // zero-init; re-armed by scan3
__device__ int      g_off[N_NODES + 1];
__device__ int      g_cur[N_NODES];
__device__ int      g_csr[N_EDGES];
__device__ int      g_bsum[SCAN_NB];
__device__ int      g_bpre[SCAN_NB];
__device__ unsigned g_pooled_u[POOL_N];          // ordered-uint encoded max
__device__ int      g_shist[SORT_BINS];          // zero-init; re-armed by scan3
__device__ int      g_scur[SORT_BINS];
__device__ int      g_perm[N_NODES];

// ---------------- helpers ----------------------------------------------------
__device__ __forceinline__ unsigned long long pack2(float lo, float hi) {
    unsigned long long r;
    asm("mov.b64 %0, {%1, %2};" : "=l"(r) : "f"(lo), "f"(hi));
    return r;
}
__device__ __forceinline__ void unpack2(unsigned long long v, float& lo, float& hi) {
    asm("mov.b64 {%0, %1}, %2;" : "=f"(lo), "=f"(hi) : "l"(v));
}
__device__ __forceinline__ void fma2(unsigned long long& acc, unsigned long long a,
                                     unsigned long long b) {
    asm("fma.rn.f32x2 %0, %1, %2, %0;" : "+l"(acc) : "l"(a), "l"(b));
}
__device__ __forceinline__ float lrelu02(float v) { return (v > 0.f) ? v : 0.2f * v; }
__device__ __forceinline__ unsigned fenc(float f) {
    unsigned u = __float_as_uint(f);
    return (u & 0x80000000u) ? ~u : (u | 0x80000000u);
}
__device__ __forceinline__ float fdec(unsigned u) {
    u = (u & 0x80000000u) ? (u & 0x7fffffffu) : ~u;
    return __uint_as_float(u);
}
#define ENC_NEG_INF 0x007fffffu   // fenc(-INFINITY)

// ---------------- 1) h = x @ W + attention logits ----------------------------
// W staged in shared memory (no LDG in the k-loop); x pairs read as LDS.128.
// Per k per warp: 3 LDS + 1 mov + 4 f32x2-FMA -> issue matches the fma pipe.
__global__ void __launch_bounds__(192) gemm_att_kernel(
    const float* __restrict__ x, const float* __restrict__ W,
    const float* __restrict__ att_s, const float* __restrict__ att_d) {
    extern __shared__ __align__(16) float sm[];
    float* Ws  = sm;                       // [F_IN][HIDDEN] 19200 floats
    float* xs2 = sm + F_IN * HIDDEN;       // [k][j] 800 floats, 16B-aligned
    __shared__ float red[6][NTILE][2];
    const int t = threadIdx.x;
    const int warp = t >> 5, lane = t & 31;

    // stage W: 4800 float4, coalesced
    {
        const float4* W4 = reinterpret_cast<const float4*>(W);
        float4* Ws4 = reinterpret_cast<float4*>(Ws);
        #pragma unroll
        for (int i = 0; i < (F_IN * HIDDEN) / (4 * 192); i++)   // 25
            Ws4[i * 192 + t] = W4[i * 192 + t];
    }
    const float ats = att_s[t];
    const float atd = att_d[t];
    __syncthreads();

    for (int tile = blockIdx.x; tile < N_TILES; tile += gridDim.x) {
        const int n0 = tile * NTILE;
        for (int idx = t; idx < F_IN * NTILE; idx += 192) {
            int j = idx / F_IN, k = idx - j * F_IN;
            xs2[k * NTILE + j] = x[(size_t)(n0 + j) * F_IN + k];
        }
        __syncthreads();

        unsigned long long a0 = 0ull, a1 = 0ull, a2 = 0ull, a3 = 0ull;
        #pragma unroll 4
        for (int k = 0; k < F_IN; k++) {
            float w = Ws[k * HIDDEN + t];              // LDS.32, conflict-free
            unsigned long long ww = pack2(w, w);
            const ulonglong2* xv =
                reinterpret_cast<const ulonglong2*>(&xs2[k * NTILE]);
            ulonglong2 xab = xv[0];                    // LDS.128: x01, x23
            ulonglong2 xcd = xv[1];                    // LDS.128: x45, x67
            fma2(a0, xab.x, ww);
            fma2(a1, xab.y, ww);
            fma2(a2, xcd.x, ww);
            fma2(a3, xcd.y, ww);
        }
        float hv[NTILE];
        unpack2(a0, hv[0], hv[1]);
        unpack2(a1, hv[2], hv[3]);
        unpack2(a2, hv[4], hv[5]);
        unpack2(a3, hv[6], hv[7]);

        #pragma unroll
        for (int j = 0; j < NTILE; j++)
            g_h[(size_t)(n0 + j) * HIDDEN + t] = hv[j];

        #pragma unroll
        for (int j = 0; j < NTILE; j++) {
            float as = hv[j] * ats, ad = hv[j] * atd;
            #pragma unroll
            for (int o = 16; o > 0; o >>= 1) {
                as += __shfl_xor_sync(0xffffffffu, as, o);
                ad += __shfl_xor_sync(0xffffffffu, ad, o);
            }
            if (lane == 0) { red[warp][j][0] = as; red[warp][j][1] = ad; }
        }
        __syncthreads();
        if (t < NTILE) {
            int j = t;
            g_as4[n0 + j] = make_float4(red[0][j][0] + red[1][j][0],
                                        red[2][j][0] + red[3][j][0],
                                        red[4][j][0] + red[5][j][0], 0.f);
            g_ad4[n0 + j] = make_float4(red[0][j][1] + red[1][j][1],
                                        red[2][j][1] + red[3][j][1],
                                        red[4][j][1] + red[5][j][1], 0.f);
        }
        __syncthreads();
    }
}

// ---------------- 2) CSR build (side stream) --------------------------------
__global__ void count_kernel(const int* __restrict__ ei) {
    int e = blockIdx.x * blockDim.x + threadIdx.x;
    if (e < N_EDGES) {
        int dst = ei[N_EDGES + e];
        if ((unsigned)dst < N_NODES) atomicAdd(&g_deg[dst], 1);
    }
}

__global__ void __launch_bounds__(SCAN_BLK) scan1_kernel() {
    __shared__ int wsum[32];
    const int t = threadIdx.x, lane = t & 31, warp = t >> 5;
    int i = blockIdx.x * SCAN_BLK + t;
    int v = (i < N_NODES) ? g_deg[i] : 0;
    int xinc = v;
    #pragma unroll
    for (int o = 1; o < 32; o <<= 1) {
        int y = __shfl_up_sync(0xffffffffu, xinc, o);
        if (lane >= o) xinc += y;
    }
    if (lane == 31) wsum[warp] = xinc;
    __syncthreads();
    if (warp == 0) {
        int s = wsum[lane];
        #pragma unroll
        for (int o = 1; o < 32; o <<= 1) {
            int y = __shfl_up_sync(0xffffffffu, s, o);
            if (lane >= o) s += y;
        }
        wsum[lane] = s;
    }
    __syncthreads();
    int wexcl = (warp == 0) ? 0 : wsum[warp - 1];
    if (i < N_NODES) g_off[i] = wexcl + xinc - v;     // block-local exclusive
    if (t == SCAN_BLK - 1) g_bsum[blockIdx.x] = wexcl + xinc;
}

__global__ void scan2_kernel() {
    __shared__ int wsum[32];
    const int t = threadIdx.x, lane = t & 31, warp = t >> 5;   // 128 threads
    int v = (t < SCAN_NB) ? g_bsum[t] : 0;
    int xinc = v;
    #pragma unroll
    for (int o = 1; o < 32; o <<= 1) {
        int y = __shfl_up_sync(0xffffffffu, xinc, o);
        if (lane >= o) xinc += y;
    }
    if (lane == 31) wsum[warp] = xinc;
    __syncthreads();
    if (warp == 0 && lane < 4) {
        int s = wsum[lane];
        for (int o = 1; o < 4; o <<= 1) {
            int y = __shfl_up_sync(0xfu, s, o);
            if (lane >= o) s += y;
        }
        wsum[lane] = s;
    }
    __syncthreads();
    int wexcl = (warp == 0) ? 0 : wsum[warp - 1];
    if (t < SCAN_NB) g_bpre[t] = wexcl + xinc - v;
    if (t == 0) g_off[N_NODES] = N_EDGES;
}

__global__ void __launch_bounds__(SCAN_BLK) scan3_kernel() {
    int i = blockIdx.x * SCAN_BLK + threadIdx.x;
    if (i < N_NODES) {
        int o = g_off[i] + g_bpre[blockIdx.x];
        g_off[i] = o;
        g_cur[i] = o;
        g_deg[i] = 0;          // re-arm degree histogram for the next replay
    }
    if (i < POOL_N) g_pooled_u[i] = ENC_NEG_INF;
    if (i < SORT_BINS) g_shist[i] = 0;   // re-arm sort histogram
}

// ---------------- 2b) degree-bucketed permutation (side stream) -------------
__global__ void sort_hist_kernel(const int* __restrict__ batch) {
    int i = blockIdx.x * blockDim.x + threadIdx.x;
    if (i < N_NODES) {
        int deg = g_off[i + 1] - g_off[i];
        int b = batch[i];
        int bin = b * DEG_BINS + min(deg, DEG_BINS - 1);
        atomicAdd(&g_shist[bin], 1);
    }
}

__global__ void __launch_bounds__(SCAN_BLK) sort_scan_kernel() {
    __shared__ int wsum[32];
    const int t = threadIdx.x, lane = t & 31, warp = t >> 5;
    int carry = 0;
    #pragma unroll
    for (int it = 0; it < SORT_BINS / SCAN_BLK; it++) {   // 8 chunks
        int i = it * SCAN_BLK + t;
        int v = g_shist[i];
        int xinc = v;
        #pragma unroll
        for (int o = 1; o < 32; o <<= 1) {
            int y = __shfl_up_sync(0xffffffffu, xinc, o);
            if (lane >= o) xinc += y;
        }
        if (lane == 31) wsum[warp] = xinc;
        __syncthreads();
        if (warp == 0) {
            int s = wsum[lane];
            #pragma unroll
            for (int o = 1; o < 32; o <<= 1) {
                int y = __shfl_up_sync(0xffffffffu, s, o);
                if (lane >= o) s += y;
            }
            wsum[lane] = s;
        }
        __syncthreads();
        int wexcl = (warp == 0) ? 0 : wsum[warp - 1];
        g_scur[i] = carry + wexcl + xinc - v;
        carry += wsum[31];
        __syncthreads();
    }
}

__global__ void sort_scatter_kernel(const int* __restrict__ batch) {
    int i = blockIdx.x * blockDim.x + threadIdx.x;
    if (i < N_NODES) {
        int deg = g_off[i + 1] - g_off[i];
        int b = batch[i];
        int bin = b * DEG_BINS + min(deg, DEG_BINS - 1);
        int pos = atomicAdd(&g_scur[bin], 1);
        g_perm[pos] = i;
    }
}

__global__ void fill_kernel(const int* __restrict__ ei) {
    int e = blockIdx.x * blockDim.x + threadIdx.x;
    if (e < N_EDGES) {
        int src = ei[e];
        int dst = ei[N_EDGES + e];
        if ((unsigned)dst < N_NODES) {
            int pos = atomicAdd(&g_cur[dst], 1);
            g_csr[pos] = src;
        }
    }
}

// ---------------- 3) single-pass softmax aggregation + fused max-pool -------
// one warp per destination node (R7 hot loop, untouched); nodes permuted so a
// block's 8 warps get near-equal degrees and stay graph-contiguous.
__global__ void __launch_bounds__(256) agg_kernel(const float* __restrict__ bias,
                                                  const int* __restrict__ batch) {
    __shared__ float smax[8][HIDDEN];
    __shared__ int sbatch[8];
    const int wid = threadIdx.x >> 5, lane = threadIdx.x & 31;
    const int slot = blockIdx.x * 8 + wid;
    const bool active = (slot < N_NODES);
    const int n = active ? g_perm[slot] : 0;

    if (active) {
        const float4 ad4 = g_ad4[n];
        const float4 asn = g_as4[n];
        const float ps0 = __expf(lrelu02(asn.x + ad4.x));
        const float ps1 = __expf(lrelu02(asn.y + ad4.y));
        const float ps2 = __expf(lrelu02(asn.z + ad4.z));
        const int beg = g_off[n];
        const int cnt_e = g_off[n + 1] - beg;
        const int total = cnt_e + 1;                 // + self loop

        float d0 = 0.f, d1 = 0.f, d2 = 0.f;
        float2 ac0 = {0.f, 0.f}, ac1 = {0.f, 0.f}, ac2 = {0.f, 0.f};

        for (int base = 0; base < total; base += 32) {
            int idx = base + lane;
            int src = n;
            float p0 = 0.f, p1 = 0.f, p2 = 0.f;
            if (idx < cnt_e) {
                src = g_csr[beg + idx];
                float4 s4 = g_as4[src];
                p0 = __expf(lrelu02(s4.x + ad4.x));
                p1 = __expf(lrelu02(s4.y + ad4.y));
                p2 = __expf(lrelu02(s4.z + ad4.z));
            } else if (idx == cnt_e) {
                p0 = ps0; p1 = ps1; p2 = ps2;
            }
            d0 += p0; d1 += p1; d2 += p2;

            const int lim = min(32, total - base);
            for (int kk = 0; kk < lim; kk++) {
                float q0 = __shfl_sync(0xffffffffu, p0, kk);
                float q1 = __shfl_sync(0xffffffffu, p1, kk);
                float q2 = __shfl_sync(0xffffffffu, p2, kk);
                int   s  = __shfl_sync(0xffffffffu, src, kk);
                const float2* h2 = reinterpret_cast<const float2*>(
                    g_h + (size_t)s * HIDDEN);
                float2 v0 = h2[lane];
                float2 v1 = h2[lane + 32];
                float2 v2 = h2[lane + 64];
                ac0.x += q0 * v0.x; ac0.y += q0 * v0.y;
                ac1.x += q1 * v1.x; ac1.y += q1 * v1.y;
                ac2.x += q2 * v2.x; ac2.y += q2 * v2.y;
            }
        }

        #pragma unroll
        for (int o = 16; o > 0; o >>= 1) {
            d0 += __shfl_xor_sync(0xffffffffu, d0, o);
            d1 += __shfl_xor_sync(0xffffffffu, d1, o);
            d2 += __shfl_xor_sync(0xffffffffu, d2, o);
        }
        const float i0 = 1.f / d0, i1 = 1.f / d1, i2 = 1.f / d2;

        const float2* b2 = reinterpret_cast<const float2*>(bias);
        float2* sp = reinterpret_cast<float2*>(smax[wid]);
        float2 bb, vv;
        bb = b2[lane];
        vv.x = ac0.x * i0 + bb.x; vv.x = (vv.x > 0.f) ? vv.x : 0.01f * vv.x;
        vv.y = ac0.y * i0 + bb.y; vv.y = (vv.y > 0.f) ? vv.y : 0.01f * vv.y;
        sp[lane] = vv;
        bb = b2[lane + 32];
        vv.x = ac1.x * i1 + bb.x; vv.x = (vv.x > 0.f) ? vv.x : 0.01f * vv.x;
        vv.y = ac1.y * i1 + bb.y; vv.y = (vv.y > 0.f) ? vv.y : 0.01f * vv.y;
        sp[lane + 32] = vv;
        bb = b2[lane + 64];
        vv.x = ac2.x * i2 + bb.x; vv.x = (vv.x > 0.f) ? vv.x : 0.01f * vv.x;
        vv.y = ac2.y * i2 + bb.y; vv.y = (vv.y > 0.f) ? vv.y : 0.01f * vv.y;
        sp[lane + 64] = vv;
        if (lane == 0) sbatch[wid] = batch[n];
    } else {
        if (lane == 0) sbatch[wid] = -1;
    }
    __syncthreads();

    // per-column run-wise max over the block's 8 nodes, then atomicMax
    if (threadIdx.x < HIDDEN) {
        const int col = threadIdx.x;
        float cur = -INFINITY;
        int curg = -2;
        #pragma unroll
        for (int w = 0; w < 8; w++) {
            int g = sbatch[w];
            if (g < 0) continue;
            if (g != curg) {
                if (curg >= 0)
                    atomicMax(&g_pooled_u[curg * HIDDEN + col], fenc(cur));
                curg = g;
                cur = -INFINITY;
            }
            cur = fmaxf(cur, smax[w][col]);
        }
        if (curg >= 0)
            atomicMax(&g_pooled_u[curg * HIDDEN + col], fenc(cur));
    }
}

// ---------------- 4) classifier ----------------------------------------------
__global__ void cls_kernel(const float* __restrict__ cw,
                           const float* __restrict__ cb,
                           float* __restrict__ out) {
    int t = threadIdx.x;               // 256 = 128 graphs * 2 classes
    int g = t >> 1, c = t & 1;
    float s = cb[c];
    #pragma unroll 4
    for (int k = 0; k < HIDDEN; k++)
        s += fdec(g_pooled_u[g * HIDDEN + k]) * cw[k * NUM_CLASSES + c];
    out[g * NUM_CLASSES + c] = s;
}

// ---------------- launch: fork CSR+sort chain onto a side stream -------------
extern "C" void kernel_launch(void* const* d_in, const int* in_sizes, int n_in,
                              void* d_out, int out_size) {
    const float* x     = (const float*)d_in[0];
    const int*   ei    = (const int*)d_in[1];
    const int*   batch = (const int*)d_in[2];
    const float* W     = (const float*)d_in[3];
    const float* att_s = (const float*)d_in[4];
    const float* att_d = (const float*)d_in[5];
    const float* bias  = (const float*)d_in[6];
    const float* cw    = (const float*)d_in[7];
    const float* cb    = (const float*)d_in[8];
    float* out = (float*)d_out;

    cudaFuncSetAttribute(gemm_att_kernel,
                         cudaFuncAttributeMaxDynamicSharedMemorySize,
                         GEMM_SMEM_BYTES);

    cudaStream_t s2;
    cudaStreamCreateWithFlags(&s2, cudaStreamNonBlocking);
    cudaEvent_t evFork, evJoin;
    cudaEventCreateWithFlags(&evFork, cudaEventDisableTiming);
    cudaEventCreateWithFlags(&evJoin, cudaEventDisableTiming);

    cudaEventRecord(evFork, 0);
    cudaStreamWaitEvent(s2, evFork, 0);

    // side stream: CSR build + degree-bucketed permutation
    count_kernel<<<(N_EDGES + 255) / 256, 256, 0, s2>>>(ei);
    scan1_kernel<<<SCAN_NB, SCAN_BLK, 0, s2>>>();
    scan2_kernel<<<1, 128, 0, s2>>>();
    scan3_kernel<<<SCAN_NB, SCAN_BLK, 0, s2>>>();
    sort_hist_kernel<<<(N_NODES + 255) / 256, 256, 0, s2>>>(batch);
    sort_scan_kernel<<<1, SCAN_BLK, 0, s2>>>();
    sort_scatter_kernel<<<(N_NODES + 255) / 256, 256, 0, s2>>>(batch);
    fill_kernel<<<(N_EDGES + 255) / 256, 256, 0, s2>>>(ei);
    cudaEventRecord(evJoin, s2);

    // main stream: GEMM runs concurrently with the CSR chain
    gemm_att_kernel<<<592, 192, GEMM_SMEM_BYTES>>>(x, W, att_s, att_d);

    // join, then aggregation + classifier on the main stream
    cudaStreamWaitEvent(0, evJoin, 0);
    agg_kernel<<<(N_NODES + 7) / 8, 256>>>(bias, batch);
    cls_kernel<<<1, 256>>>(cw, cb, out);

    cudaEventDestroy(evFork);
    cudaEventDestroy(evJoin);
    cudaStreamDestroy(s2);
}

// round 14
// speedup vs baseline: 1.2077x; 1.2077x over previous
#include <cuda_runtime.h>
#include <math.h>

#define N_NODES    100000
#define N_EDGES    1600000
#define F_IN       100
#define HEADS      3
#define HEAD_DIM   64
#define HIDDEN     192
#define NUM_GRAPHS 128
#define NUM_CLASSES 2
#define NTILE      16
#define N_TILES    (N_NODES / NTILE)   // 6250
#define SCAN_BLK   1024
#define SCAN_NB    ((N_NODES + SCAN_BLK - 1) / SCAN_BLK)   // 98
#define POOL_N     (NUM_GRAPHS * HIDDEN)                   // 24576
#define DEG_BINS   64
#define SORT_BINS  (NUM_GRAPHS * DEG_BINS)                 // 8192

// ---------------- scratch (device globals; no allocations allowed) ----------
__device__ float    g_h[N_NODES * HIDDEN];       // 76.8 MB fp32
__device__ float4   g_as4[N_NODES];              // a_src per node (xyz used)
__device__ float4   g_ad4[N_NODES];              // a_dst per node
__device__ int      g_deg[N_NODES];              // zero-init; re-armed by scan3
__device__ int      g_off[N_NODES + 1];
__device__ int      g_cur[N_NODES];
__device__ int      g_csr[N_EDGES];
__device__ int      g_bsum[SCAN_NB];
__device__ int      g_bpre[SCAN_NB];
__device__ unsigned g_pooled_u[POOL_N];          // ordered-uint encoded max
__device__ int      g_shist[SORT_BINS];          // zero-init; re-armed by scan3
__device__ int      g_scur[SORT_BINS];
__device__ int      g_perm[N_NODES];

// ---------------- helpers ----------------------------------------------------
__device__ __forceinline__ unsigned long long pack2(float lo, float hi) {
    unsigned long long r;
    asm("mov.b64 %0, {%1, %2};" : "=l"(r) : "f"(lo), "f"(hi));
    return r;
}
__device__ __forceinline__ void unpack2(unsigned long long v, float& lo, float& hi) {
    asm("mov.b64 {%0, %1}, %2;" : "=f"(lo), "=f"(hi) : "l"(v));
}
__device__ __forceinline__ void fma2(unsigned long long& acc, unsigned long long a,
                                     unsigned long long b) {
    asm("fma.rn.f32x2 %0, %1, %2, %0;" : "+l"(acc) : "l"(a), "l"(b));
}
__device__ __forceinline__ float lrelu02(float v) { return (v > 0.f) ? v : 0.2f * v; }
__device__ __forceinline__ unsigned fenc(float f) {
    unsigned u = __float_as_uint(f);
    return (u & 0x80000000u) ? ~u : (u | 0x80000000u);
}
__device__ __forceinline__ float fdec(unsigned u) {
    u = (u & 0x80000000u) ? (u & 0x7fffffffu) : ~u;
    return __uint_as_float(u);
}
#define ENC_NEG_INF 0x007fffffu   // fenc(-INFINITY)

// ---------------- 1) h = x @ W + attention logits ----------------------------
// High-occupancy form (W via LDG, small static smem). NTILE=16: one W load
// feeds 8 f32x2-FMAs; x pairs read as 4x LDS.128.
__global__ void __launch_bounds__(192) gemm_att_kernel(
    const float* __restrict__ x, const float* __restrict__ W,
    const float* __restrict__ att_s, const float* __restrict__ att_d) {
    __shared__ __align__(16) float xs2[F_IN * NTILE];       // [k][j] 6.4 KB
    __shared__ float red[6][NTILE][2];
    const int t = threadIdx.x;
    const int warp = t >> 5, lane = t & 31;
    const float ats = att_s[t];
    const float atd = att_d[t];

    for (int tile = blockIdx.x; tile < N_TILES; tile += gridDim.x) {
        const int n0 = tile * NTILE;
        for (int idx = t; idx < F_IN * NTILE; idx += 192) {
            int j = idx / F_IN, k = idx - j * F_IN;
            xs2[k * NTILE + j] = x[(size_t)(n0 + j) * F_IN + k];
        }
        __syncthreads();

        unsigned long long a0 = 0ull, a1 = 0ull, a2 = 0ull, a3 = 0ull;
        unsigned long long a4 = 0ull, a5 = 0ull, a6 = 0ull, a7 = 0ull;
        #pragma unroll 4
        for (int k = 0; k < F_IN; k++) {
            float w = W[k * HIDDEN + t];
            unsigned long long ww = pack2(w, w);
            const ulonglong2* xv =
                reinterpret_cast<const ulonglong2*>(&xs2[k * NTILE]);
            ulonglong2 xab = xv[0];                    // LDS.128
            ulonglong2 xcd = xv[1];
            ulonglong2 xef = xv[2];
            ulonglong2 xgh = xv[3];
            fma2(a0, xab.x, ww);
            fma2(a1, xab.y, ww);
            fma2(a2, xcd.x, ww);
            fma2(a3, xcd.y, ww);
            fma2(a4, xef.x, ww);
            fma2(a5, xef.y, ww);
            fma2(a6, xgh.x, ww);
            fma2(a7, xgh.y, ww);
        }
        float hv[NTILE];
        unpack2(a0, hv[0],  hv[1]);
        unpack2(a1, hv[2],  hv[3]);
        unpack2(a2, hv[4],  hv[5]);
        unpack2(a3, hv[6],  hv[7]);
        unpack2(a4, hv[8],  hv[9]);
        unpack2(a5, hv[10], hv[11]);
        unpack2(a6, hv[12], hv[13]);
        unpack2(a7, hv[14], hv[15]);

        #pragma unroll
        for (int j = 0; j < NTILE; j++)
            g_h[(size_t)(n0 + j) * HIDDEN + t] = hv[j];

        #pragma unroll
        for (int j = 0; j < NTILE; j++) {
            float as = hv[j] * ats, ad = hv[j] * atd;
            #pragma unroll
            for (int o = 16; o > 0; o >>= 1) {
                as += __shfl_xor_sync(0xffffffffu, as, o);
                ad += __shfl_xor_sync(0xffffffffu, ad, o);
            }
            if (lane == 0) { red[warp][j][0] = as; red[warp][j][1] = ad; }
        }
        __syncthreads();
        if (t < NTILE) {
            int j = t;
            g_as4[n0 + j] = make_float4(red[0][j][0] + red[1][j][0],
                                        red[2][j][0] + red[3][j][0],
                                        red[4][j][0] + red[5][j][0], 0.f);
            g_ad4[n0 + j] = make_float4(red[0][j][1] + red[1][j][1],
                                        red[2][j][1] + red[3][j][1],
                                        red[4][j][1] + red[5][j][1], 0.f);
        }
        __syncthreads();
    }
}

// ---------------- 2) CSR build (side stream) --------------------------------
__global__ void count_kernel(const int* __restrict__ ei) {
    int e = blockIdx.x * blockDim.x + threadIdx.x;
    if (e < N_EDGES) {
        int dst = ei[N_EDGES + e];
        if ((unsigned)dst < N_NODES) atomicAdd(&g_deg[dst], 1);
    }
}

__global__ void __launch_bounds__(SCAN_BLK) scan1_kernel() {
    __shared__ int wsum[32];
    const int t = threadIdx.x, lane = t & 31, warp = t >> 5;
    int i = blockIdx.x * SCAN_BLK + t;
    int v = (i < N_NODES) ? g_deg[i] : 0;
    int xinc = v;
    #pragma unroll
    for (int o = 1; o < 32; o <<= 1) {
        int y = __shfl_up_sync(0xffffffffu, xinc, o);
        if (lane >= o) xinc += y;
    }
    if (lane == 31) wsum[warp] = xinc;
    __syncthreads();
    if (warp == 0) {
        int s = wsum[lane];
        #pragma unroll
        for (int o = 1; o < 32; o <<= 1) {
            int y = __shfl_up_sync(0xffffffffu, s, o);
            if (lane >= o) s += y;
        }
        wsum[lane] = s;
    }
    __syncthreads();
    int wexcl = (warp == 0) ? 0 : wsum[warp - 1];
    if (i < N_NODES) g_off[i] = wexcl + xinc - v;     // block-local exclusive
    if (t == SCAN_BLK - 1) g_bsum[blockIdx.x] = wexcl + xinc;
}

__global__ void scan2_kernel() {
    __shared__ int wsum[32];
    const int t = threadIdx.x, lane = t & 31, warp = t >> 5;   // 128 threads
    int v = (t < SCAN_NB) ? g_bsum[t] : 0;
    int xinc = v;
    #pragma unroll
    for (int o = 1; o < 32; o <<= 1) {
        int y = __shfl_up_sync(0xffffffffu, xinc, o);
        if (lane >= o) xinc += y;
    }
    if (lane == 31) wsum[warp] = xinc;
    __syncthreads();
    if (warp == 0 && lane < 4) {
        int s = wsum[lane];
        for (int o = 1; o < 4; o <<= 1) {
            int y = __shfl_up_sync(0xfu, s, o);
            if (lane >= o) s += y;
        }
        wsum[lane] = s;
    }
    __syncthreads();
    int wexcl = (warp == 0) ? 0 : wsum[warp - 1];
    if (t < SCAN_NB) g_bpre[t] = wexcl + xinc - v;
    if (t == 0) g_off[N_NODES] = N_EDGES;
}

__global__ void __launch_bounds__(SCAN_BLK) scan3_kernel() {
    int i = blockIdx.x * SCAN_BLK + threadIdx.x;
    if (i < N_NODES) {
        int o = g_off[i] + g_bpre[blockIdx.x];
        g_off[i] = o;
        g_cur[i] = o;
        g_deg[i] = 0;          // re-arm degree histogram for the next replay
    }
    if (i < POOL_N) g_pooled_u[i] = ENC_NEG_INF;
    if (i < SORT_BINS) g_shist[i] = 0;   // re-arm sort histogram
}

// ---------------- 2b) degree-bucketed permutation (side stream) -------------
__global__ void sort_hist_kernel(const int* __restrict__ batch) {
    int i = blockIdx.x * blockDim.x + threadIdx.x;
    if (i < N_NODES) {
        int deg = g_off[i + 1] - g_off[i];
        int b = batch[i];
        int bin = b * DEG_BINS + min(deg, DEG_BINS - 1);
        atomicAdd(&g_shist[bin], 1);
    }
}

__global__ void __launch_bounds__(SCAN_BLK) sort_scan_kernel() {
    __shared__ int wsum[32];
    const int t = threadIdx.x, lane = t & 31, warp = t >> 5;
    int carry = 0;
    #pragma unroll
    for (int it = 0; it < SORT_BINS / SCAN_BLK; it++) {   // 8 chunks
        int i = it * SCAN_BLK + t;
        int v = g_shist[i];
        int xinc = v;
        #pragma unroll
        for (int o = 1; o < 32; o <<= 1) {
            int y = __shfl_up_sync(0xffffffffu, xinc, o);
            if (lane >= o) xinc += y;
        }
        if (lane == 31) wsum[warp] = xinc;
        __syncthreads();
        if (warp == 0) {
            int s = wsum[lane];
            #pragma unroll
            for (int o = 1; o < 32; o <<= 1) {
                int y = __shfl_up_sync(0xffffffffu, s, o);
                if (lane >= o) s += y;
            }
            wsum[lane] = s;
        }
        __syncthreads();
        int wexcl = (warp == 0) ? 0 : wsum[warp - 1];
        g_scur[i] = carry + wexcl + xinc - v;
        carry += wsum[31];
        __syncthreads();
    }
}

__global__ void sort_scatter_kernel(const int* __restrict__ batch) {
    int i = blockIdx.x * blockDim.x + threadIdx.x;
    if (i < N_NODES) {
        int deg = g_off[i + 1] - g_off[i];
        int b = batch[i];
        int bin = b * DEG_BINS + min(deg, DEG_BINS - 1);
        int pos = atomicAdd(&g_scur[bin], 1);
        g_perm[pos] = i;
    }
}

__global__ void fill_kernel(const int* __restrict__ ei) {
    int e = blockIdx.x * blockDim.x + threadIdx.x;
    if (e < N_EDGES) {
        int src = ei[e];
        int dst = ei[N_EDGES + e];
        if ((unsigned)dst < N_NODES) {
            int pos = atomicAdd(&g_cur[dst], 1);
            g_csr[pos] = src;
        }
    }
}

// ---------------- 3) single-pass softmax aggregation + fused max-pool -------
// one warp per destination node (R7 hot loop, untouched); nodes permuted so a
// block's 8 warps get near-equal degrees and stay graph-contiguous.
__global__ void __launch_bounds__(256) agg_kernel(const float* __restrict__ bias,
                                                  const int* __restrict__ batch) {
    __shared__ float smax[8][HIDDEN];
    __shared__ int sbatch[8];
    const int wid = threadIdx.x >> 5, lane = threadIdx.x & 31;
    const int slot = blockIdx.x * 8 + wid;
    const bool active = (slot < N_NODES);
    const int n = active ? g_perm[slot] : 0;

    if (active) {
        const float4 ad4 = g_ad4[n];
        const float4 asn = g_as4[n];
        const float ps0 = __expf(lrelu02(asn.x + ad4.x));
        const float ps1 = __expf(lrelu02(asn.y + ad4.y));
        const float ps2 = __expf(lrelu02(asn.z + ad4.z));
        const int beg = g_off[n];
        const int cnt_e = g_off[n + 1] - beg;
        const int total = cnt_e + 1;                 // + self loop

        float d0 = 0.f, d1 = 0.f, d2 = 0.f;
        float2 ac0 = {0.f, 0.f}, ac1 = {0.f, 0.f}, ac2 = {0.f, 0.f};

        for (int base = 0; base < total; base += 32) {
            int idx = base + lane;
            int src = n;
            float p0 = 0.f, p1 = 0.f, p2 = 0.f;
            if (idx < cnt_e) {
                src = g_csr[beg + idx];
                float4 s4 = g_as4[src];
                p0 = __expf(lrelu02(s4.x + ad4.x));
                p1 = __expf(lrelu02(s4.y + ad4.y));
                p2 = __expf(lrelu02(s4.z + ad4.z));
            } else if (idx == cnt_e) {
                p0 = ps0; p1 = ps1; p2 = ps2;
            }
            d0 += p0; d1 += p1; d2 += p2;

            const int lim = min(32, total - base);
            for (int kk = 0; kk < lim; kk++) {
                float q0 = __shfl_sync(0xffffffffu, p0, kk);
                float q1 = __shfl_sync(0xffffffffu, p1, kk);
                float q2 = __shfl_sync(0xffffffffu, p2, kk);
                int   s  = __shfl_sync(0xffffffffu, src, kk);
                const float2* h2 = reinterpret_cast<const float2*>(
                    g_h + (size_t)s * HIDDEN);
                float2 v0 = h2[lane];
                float2 v1 = h2[lane + 32];
                float2 v2 = h2[lane + 64];
                ac0.x += q0 * v0.x; ac0.y += q0 * v0.y;
                ac1.x += q1 * v1.x; ac1.y += q1 * v1.y;
                ac2.x += q2 * v2.x; ac2.y += q2 * v2.y;
            }
        }

        #pragma unroll
        for (int o = 16; o > 0; o >>= 1) {
            d0 += __shfl_xor_sync(0xffffffffu, d0, o);
            d1 += __shfl_xor_sync(0xffffffffu, d1, o);
            d2 += __shfl_xor_sync(0xffffffffu, d2, o);
        }
        const float i0 = 1.f / d0, i1 = 1.f / d1, i2 = 1.f / d2;

        const float2* b2 = reinterpret_cast<const float2*>(bias);
        float2* sp = reinterpret_cast<float2*>(smax[wid]);
        float2 bb, vv;
        bb = b2[lane];
        vv.x = ac0.x * i0 + bb.x; vv.x = (vv.x > 0.f) ? vv.x : 0.01f * vv.x;
        vv.y = ac0.y * i0 + bb.y; vv.y = (vv.y > 0.f) ? vv.y : 0.01f * vv.y;
        sp[lane] = vv;
        bb = b2[lane + 32];
        vv.x = ac1.x * i1 + bb.x; vv.x = (vv.x > 0.f) ? vv.x : 0.01f * vv.x;
        vv.y = ac1.y * i1 + bb.y; vv.y = (vv.y > 0.f) ? vv.y : 0.01f * vv.y;
        sp[lane + 32] = vv;
        bb = b2[lane + 64];
        vv.x = ac2.x * i2 + bb.x; vv.x = (vv.x > 0.f) ? vv.x : 0.01f * vv.x;
        vv.y = ac2.y * i2 + bb.y; vv.y = (vv.y > 0.f) ? vv.y : 0.01f * vv.y;
        sp[lane + 64] = vv;
        if (lane == 0) sbatch[wid] = batch[n];
    } else {
        if (lane == 0) sbatch[wid] = -1;
    }
    __syncthreads();

    // per-column run-wise max over the block's 8 nodes, then atomicMax
    if (threadIdx.x < HIDDEN) {
        const int col = threadIdx.x;
        float cur = -INFINITY;
        int curg = -2;
        #pragma unroll
        for (int w = 0; w < 8; w++) {
            int g = sbatch[w];
            if (g < 0) continue;
            if (g != curg) {
                if (curg >= 0)
                    atomicMax(&g_pooled_u[curg * HIDDEN + col], fenc(cur));
                curg = g;
                cur = -INFINITY;
            }
            cur = fmaxf(cur, smax[w][col]);
        }
        if (curg >= 0)
            atomicMax(&g_pooled_u[curg * HIDDEN + col], fenc(cur));
    }
}

// ---------------- 4) classifier ----------------------------------------------
__global__ void cls_kernel(const float* __restrict__ cw,
                           const float* __restrict__ cb,
                           float* __restrict__ out) {
    int t = threadIdx.x;               // 256 = 128 graphs * 2 classes
    int g = t >> 1, c = t & 1;
    float s = cb[c];
    #pragma unroll 4
    for (int k = 0; k < HIDDEN; k++)
        s += fdec(g_pooled_u[g * HIDDEN + k]) * cw[k * NUM_CLASSES + c];
    out[g * NUM_CLASSES + c] = s;
}

// ---------------- launch: fork CSR+sort chain onto a side stream -------------
extern "C" void kernel_launch(void* const* d_in, const int* in_sizes, int n_in,
                              void* d_out, int out_size) {
    const float* x     = (const float*)d_in[0];
    const int*   ei    = (const int*)d_in[1];
    const int*   batch = (const int*)d_in[2];
    const float* W     = (const float*)d_in[3];
    const float* att_s = (const float*)d_in[4];
    const float* att_d = (const float*)d_in[5];
    const float* bias  = (const float*)d_in[6];
    const float* cw    = (const float*)d_in[7];
    const float* cb    = (const float*)d_in[8];
    float* out = (float*)d_out;

    cudaStream_t s2;
    cudaStreamCreateWithFlags(&s2, cudaStreamNonBlocking);
    cudaEvent_t evFork, evJoin;
    cudaEventCreateWithFlags(&evFork, cudaEventDisableTiming);
    cudaEventCreateWithFlags(&evJoin, cudaEventDisableTiming);

    cudaEventRecord(evFork, 0);
    cudaStreamWaitEvent(s2, evFork, 0);

    // side stream: CSR build + degree-bucketed permutation
    count_kernel<<<(N_EDGES + 255) / 256, 256, 0, s2>>>(ei);
    scan1_kernel<<<SCAN_NB, SCAN_BLK, 0, s2>>>();
    scan2_kernel<<<1, 128, 0, s2>>>();
    scan3_kernel<<<SCAN_NB, SCAN_BLK, 0, s2>>>();
    sort_hist_kernel<<<(N_NODES + 255) / 256, 256, 0, s2>>>(batch);
    sort_scan_kernel<<<1, SCAN_BLK, 0, s2>>>();
    sort_scatter_kernel<<<(N_NODES + 255) / 256, 256, 0, s2>>>(batch);
    fill_kernel<<<(N_EDGES + 255) / 256, 256, 0, s2>>>(ei);
    cudaEventRecord(evJoin, s2);

    // main stream: GEMM runs concurrently with the CSR chain
    gemm_att_kernel<<<1480, 192>>>(x, W, att_s, att_d);

    // join, then aggregation + classifier on the main stream
    cudaStreamWaitEvent(0, evJoin, 0);
    agg_kernel<<<(N_NODES + 7) / 8, 256>>>(bias, batch);
    cls_kernel<<<1, 256>>>(cw, cb, out);

    cudaEventDestroy(evFork);
    cudaEventDestroy(evJoin);
    cudaStreamDestroy(s2);
}

// round 16
// speedup vs baseline: 1.2308x; 1.0192x over previous
#include <cuda_runtime.h>
#include <math.h>

#define N_NODES    100000
#define N_EDGES    1600000
#define F_IN       100
#define HEADS      3
#define HEAD_DIM   64
#define HIDDEN     192
#define NUM_GRAPHS 128
#define NUM_CLASSES 2
#define NTILE      16
#define N_TILES    (N_NODES / NTILE)   // 6250
#define SCAN_BLK   1024
#define SCAN_NB    ((N_NODES + SCAN_BLK - 1) / SCAN_BLK)   // 98
#define POOL_N     (NUM_GRAPHS * HIDDEN)                   // 24576
#define DEG_BINS   64
#define SORT_BINS  (NUM_GRAPHS * DEG_BINS)                 // 8192

// ---------------- scratch (device globals; no allocations allowed) ----------
__device__ float    g_h[N_NODES * HIDDEN];       // 76.8 MB fp32
__device__ float4   g_as4[N_NODES];              // a_src per node (xyz used)
__device__ float4   g_ad4[N_NODES];              // a_dst per node
__device__ int      g_deg[N_NODES];              // zero-init; re-armed by scan3
__device__ int      g_off[N_NODES + 1];
__device__ int      g_cur[N_NODES];
__device__ int      g_csr[N_EDGES];
__device__ int      g_bsum[SCAN_NB];
__device__ int      g_bpre[SCAN_NB];
__device__ unsigned g_pooled_u[POOL_N];          // ordered-uint encoded max
__device__ int      g_shist[SORT_BINS];          // zero-init; re-armed by scan3
__device__ int      g_scur[SORT_BINS];
__device__ int      g_perm[N_NODES];

// ---------------- helpers ----------------------------------------------------
__device__ __forceinline__ unsigned long long pack2(float lo, float hi) {
    unsigned long long r;
    asm("mov.b64 %0, {%1, %2};" : "=l"(r) : "f"(lo), "f"(hi));
    return r;
}
__device__ __forceinline__ void unpack2(unsigned long long v, float& lo, float& hi) {
    asm("mov.b64 {%0, %1}, %2;" : "=f"(lo), "=f"(hi) : "l"(v));
}
__device__ __forceinline__ void fma2(unsigned long long& acc, unsigned long long a,
                                     unsigned long long b) {
    asm("fma.rn.f32x2 %0, %1, %2, %0;" : "+l"(acc) : "l"(a), "l"(b));
}
__device__ __forceinline__ float lrelu02(float v) { return (v > 0.f) ? v : 0.2f * v; }
__device__ __forceinline__ unsigned fenc(float f) {
    unsigned u = __float_as_uint(f);
    return (u & 0x80000000u) ? ~u : (u | 0x80000000u);
}
__device__ __forceinline__ float fdec(unsigned u) {
    u = (u & 0x80000000u) ? (u & 0x7fffffffu) : ~u;
    return __uint_as_float(u);
}
#define ENC_NEG_INF 0x007fffffu   // fenc(-INFINITY)

// ---------------- 1) h = x @ W + attention logits ----------------------------
// High-occupancy form (W via LDG, small static smem). NTILE=16: one W load
// feeds 8 f32x2-FMAs; x pairs read as 4x LDS.128.
__global__ void __launch_bounds__(192) gemm_att_kernel(
    const float* __restrict__ x, const float* __restrict__ W,
    const float* __restrict__ att_s, const float* __restrict__ att_d) {
    __shared__ __align__(16) float xs2[F_IN * NTILE];       // [k][j] 6.4 KB
    __shared__ float red[6][NTILE][2];
    const int t = threadIdx.x;
    const int warp = t >> 5, lane = t & 31;
    const float ats = att_s[t];
    const float atd = att_d[t];

    for (int tile = blockIdx.x; tile < N_TILES; tile += gridDim.x) {
        const int n0 = tile * NTILE;
        for (int idx = t; idx < F_IN * NTILE; idx += 192) {
            int j = idx / F_IN, k = idx - j * F_IN;
            xs2[k * NTILE + j] = x[(size_t)(n0 + j) * F_IN + k];
        }
        __syncthreads();

        unsigned long long a0 = 0ull, a1 = 0ull, a2 = 0ull, a3 = 0ull;
        unsigned long long a4 = 0ull, a5 = 0ull, a6 = 0ull, a7 = 0ull;
        #pragma unroll 4
        for (int k = 0; k < F_IN; k++) {
            float w = W[k * HIDDEN + t];
            unsigned long long ww = pack2(w, w);
            const ulonglong2* xv =
                reinterpret_cast<const ulonglong2*>(&xs2[k * NTILE]);
            ulonglong2 xab = xv[0];                    // LDS.128
            ulonglong2 xcd = xv[1];
            ulonglong2 xef = xv[2];
            ulonglong2 xgh = xv[3];
            fma2(a0, xab.x, ww);
            fma2(a1, xab.y, ww);
            fma2(a2, xcd.x, ww);
            fma2(a3, xcd.y, ww);
            fma2(a4, xef.x, ww);
            fma2(a5, xef.y, ww);
            fma2(a6, xgh.x, ww);
            fma2(a7, xgh.y, ww);
        }
        float hv[NTILE];
        unpack2(a0, hv[0],  hv[1]);
        unpack2(a1, hv[2],  hv[3]);
        unpack2(a2, hv[4],  hv[5]);
        unpack2(a3, hv[6],  hv[7]);
        unpack2(a4, hv[8],  hv[9]);
        unpack2(a5, hv[10], hv[11]);
        unpack2(a6, hv[12], hv[13]);
        unpack2(a7, hv[14], hv[15]);

        #pragma unroll
        for (int j = 0; j < NTILE; j++)
            g_h[(size_t)(n0 + j) * HIDDEN + t] = hv[j];

        #pragma unroll
        for (int j = 0; j < NTILE; j++) {
            float as = hv[j] * ats, ad = hv[j] * atd;
            #pragma unroll
            for (int o = 16; o > 0; o >>= 1) {
                as += __shfl_xor_sync(0xffffffffu, as, o);
                ad += __shfl_xor_sync(0xffffffffu, ad, o);
            }
            if (lane == 0) { red[warp][j][0] = as; red[warp][j][1] = ad; }
        }
        __syncthreads();
        if (t < NTILE) {
            int j = t;
            g_as4[n0 + j] = make_float4(red[0][j][0] + red[1][j][0],
                                        red[2][j][0] + red[3][j][0],
                                        red[4][j][0] + red[5][j][0], 0.f);
            g_ad4[n0 + j] = make_float4(red[0][j][1] + red[1][j][1],
                                        red[2][j][1] + red[3][j][1],
                                        red[4][j][1] + red[5][j][1], 0.f);
        }
        __syncthreads();
    }
}

// ---------------- 2) CSR build (side stream) --------------------------------
__global__ void count_kernel(const int* __restrict__ ei) {
    int e = blockIdx.x * blockDim.x + threadIdx.x;
    if (e < N_EDGES) {
        int dst = ei[N_EDGES + e];
        if ((unsigned)dst < N_NODES) atomicAdd(&g_deg[dst], 1);
    }
}

__global__ void __launch_bounds__(SCAN_BLK) scan1_kernel() {
    __shared__ int wsum[32];
    const int t = threadIdx.x, lane = t & 31, warp = t >> 5;
    int i = blockIdx.x * SCAN_BLK + t;
    int v = (i < N_NODES) ? g_deg[i] : 0;
    int xinc = v;
    #pragma unroll
    for (int o = 1; o < 32; o <<= 1) {
        int y = __shfl_up_sync(0xffffffffu, xinc, o);
        if (lane >= o) xinc += y;
    }
    if (lane == 31) wsum[warp] = xinc;
    __syncthreads();
    if (warp == 0) {
        int s = wsum[lane];
        #pragma unroll
        for (int o = 1; o < 32; o <<= 1) {
            int y = __shfl_up_sync(0xffffffffu, s, o);
            if (lane >= o) s += y;
        }
        wsum[lane] = s;
    }
    __syncthreads();
    int wexcl = (warp == 0) ? 0 : wsum[warp - 1];
    if (i < N_NODES) g_off[i] = wexcl + xinc - v;     // block-local exclusive
    if (t == SCAN_BLK - 1) g_bsum[blockIdx.x] = wexcl + xinc;
}

__global__ void scan2_kernel() {
    __shared__ int wsum[32];
    const int t = threadIdx.x, lane = t & 31, warp = t >> 5;   // 128 threads
    int v = (t < SCAN_NB) ? g_bsum[t] : 0;
    int xinc = v;
    #pragma unroll
    for (int o = 1; o < 32; o <<= 1) {
        int y = __shfl_up_sync(0xffffffffu, xinc, o);
        if (lane >= o) xinc += y;
    }
    if (lane == 31) wsum[warp] = xinc;
    __syncthreads();
    if (warp == 0 && lane < 4) {
        int s = wsum[lane];
        for (int o = 1; o < 4; o <<= 1) {
            int y = __shfl_up_sync(0xfu, s, o);
            if (lane >= o) s += y;
        }
        wsum[lane] = s;
    }
    __syncthreads();
    int wexcl = (warp == 0) ? 0 : wsum[warp - 1];
    if (t < SCAN_NB) g_bpre[t] = wexcl + xinc - v;
    if (t == 0) g_off[N_NODES] = N_EDGES;
}

__global__ void __launch_bounds__(SCAN_BLK) scan3_kernel() {
    int i = blockIdx.x * SCAN_BLK + threadIdx.x;
    if (i < N_NODES) {
        int o = g_off[i] + g_bpre[blockIdx.x];
        g_off[i] = o;
        g_cur[i] = o;
        g_deg[i] = 0;          // re-arm degree histogram for the next replay
    }
    if (i < POOL_N) g_pooled_u[i] = ENC_NEG_INF;
    if (i < SORT_BINS) g_shist[i] = 0;   // re-arm sort histogram
}

// ---------------- 2b) degree-bucketed permutation (side stream) -------------
__global__ void sort_hist_kernel(const int* __restrict__ batch) {
    int i = blockIdx.x * blockDim.x + threadIdx.x;
    if (i < N_NODES) {
        int deg = g_off[i + 1] - g_off[i];
        int b = batch[i];
        int bin = b * DEG_BINS + min(deg, DEG_BINS - 1);
        atomicAdd(&g_shist[bin], 1);
    }
}

__global__ void __launch_bounds__(SCAN_BLK) sort_scan_kernel() {
    __shared__ int wsum[32];
    const int t = threadIdx.x, lane = t & 31, warp = t >> 5;
    int carry = 0;
    #pragma unroll
    for (int it = 0; it < SORT_BINS / SCAN_BLK; it++) {   // 8 chunks
        int i = it * SCAN_BLK + t;
        int v = g_shist[i];
        int xinc = v;
        #pragma unroll
        for (int o = 1; o < 32; o <<= 1) {
            int y = __shfl_up_sync(0xffffffffu, xinc, o);
            if (lane >= o) xinc += y;
        }
        if (lane == 31) wsum[warp] = xinc;
        __syncthreads();
        if (warp == 0) {
            int s = wsum[lane];
            #pragma unroll
            for (int o = 1; o < 32; o <<= 1) {
                int y = __shfl_up_sync(0xffffffffu, s, o);
                if (lane >= o) s += y;
            }
            wsum[lane] = s;
        }
        __syncthreads();
        int wexcl = (warp == 0) ? 0 : wsum[warp - 1];
        g_scur[i] = carry + wexcl + xinc - v;
        carry += wsum[31];
        __syncthreads();
    }
}

__global__ void sort_scatter_kernel(const int* __restrict__ batch) {
    int i = blockIdx.x * blockDim.x + threadIdx.x;
    if (i < N_NODES) {
        int deg = g_off[i + 1] - g_off[i];
        int b = batch[i];
        int bin = b * DEG_BINS + min(deg, DEG_BINS - 1);
        int pos = atomicAdd(&g_scur[bin], 1);
        g_perm[pos] = i;
    }
}

__global__ void fill_kernel(const int* __restrict__ ei) {
    int e = blockIdx.x * blockDim.x + threadIdx.x;
    if (e < N_EDGES) {
        int src = ei[e];
        int dst = ei[N_EDGES + e];
        if ((unsigned)dst < N_NODES) {
            int pos = atomicAdd(&g_cur[dst], 1);
            g_csr[pos] = src;
        }
    }
}

// ---------------- 3) single-pass softmax aggregation + fused max-pool -------
// one warp per destination node; broadcast loop unrolled x2 (two independent
// h-row LDG chains in flight halves the warp count needed to cover L2 latency).
__global__ void __launch_bounds__(256) agg_kernel(const float* __restrict__ bias,
                                                  const int* __restrict__ batch) {
    __shared__ float smax[8][HIDDEN];
    __shared__ int sbatch[8];
    const int wid = threadIdx.x >> 5, lane = threadIdx.x & 31;
    const int slot = blockIdx.x * 8 + wid;
    const bool active = (slot < N_NODES);
    const int n = active ? g_perm[slot] : 0;

    if (active) {
        const float4 ad4 = g_ad4[n];
        const float4 asn = g_as4[n];
        const float ps0 = __expf(lrelu02(asn.x + ad4.x));
        const float ps1 = __expf(lrelu02(asn.y + ad4.y));
        const float ps2 = __expf(lrelu02(asn.z + ad4.z));
        const int beg = g_off[n];
        const int cnt_e = g_off[n + 1] - beg;
        const int total = cnt_e + 1;                 // + self loop

        float d0 = 0.f, d1 = 0.f, d2 = 0.f;
        float2 ac0 = {0.f, 0.f}, ac1 = {0.f, 0.f}, ac2 = {0.f, 0.f};

        for (int base = 0; base < total; base += 32) {
            int idx = base + lane;
            int src = n;
            float p0 = 0.f, p1 = 0.f, p2 = 0.f;
            if (idx < cnt_e) {
                src = g_csr[beg + idx];
                float4 s4 = g_as4[src];
                p0 = __expf(lrelu02(s4.x + ad4.x));
                p1 = __expf(lrelu02(s4.y + ad4.y));
                p2 = __expf(lrelu02(s4.z + ad4.z));
            } else if (idx == cnt_e) {
                p0 = ps0; p1 = ps1; p2 = ps2;
            }
            d0 += p0; d1 += p1; d2 += p2;

            const int lim = min(32, total - base);
            int kk = 0;
            for (; kk + 2 <= lim; kk += 2) {
                int sA = __shfl_sync(0xffffffffu, src, kk);
                int sB = __shfl_sync(0xffffffffu, src, kk + 1);
                const float2* hA = reinterpret_cast<const float2*>(
                    g_h + (size_t)sA * HIDDEN);
                const float2* hB = reinterpret_cast<const float2*>(
                    g_h + (size_t)sB * HIDDEN);
                float2 vA0 = hA[lane], vA1 = hA[lane + 32], vA2 = hA[lane + 64];
                float2 vB0 = hB[lane], vB1 = hB[lane + 32], vB2 = hB[lane + 64];
                float qA0 = __shfl_sync(0xffffffffu, p0, kk);
                float qA1 = __shfl_sync(0xffffffffu, p1, kk);
                float qA2 = __shfl_sync(0xffffffffu, p2, kk);
                float qB0 = __shfl_sync(0xffffffffu, p0, kk + 1);
                float qB1 = __shfl_sync(0xffffffffu, p1, kk + 1);
                float qB2 = __shfl_sync(0xffffffffu, p2, kk + 1);
                ac0.x += qA0 * vA0.x; ac0.y += qA0 * vA0.y;
                ac1.x += qA1 * vA1.x; ac1.y += qA1 * vA1.y;
                ac2.x += qA2 * vA2.x; ac2.y += qA2 * vA2.y;
                ac0.x += qB0 * vB0.x; ac0.y += qB0 * vB0.y;
                ac1.x += qB1 * vB1.x; ac1.y += qB1 * vB1.y;
                ac2.x += qB2 * vB2.x; ac2.y += qB2 * vB2.y;
            }
            if (kk < lim) {
                float q0 = __shfl_sync(0xffffffffu, p0, kk);
                float q1 = __shfl_sync(0xffffffffu, p1, kk);
                float q2 = __shfl_sync(0xffffffffu, p2, kk);
                int   s  = __shfl_sync(0xffffffffu, src, kk);
                const float2* h2 = reinterpret_cast<const float2*>(
                    g_h + (size_t)s * HIDDEN);
                float2 v0 = h2[lane];
                float2 v1 = h2[lane + 32];
                float2 v2 = h2[lane + 64];
                ac0.x += q0 * v0.x; ac0.y += q0 * v0.y;
                ac1.x += q1 * v1.x; ac1.y += q1 * v1.y;
                ac2.x += q2 * v2.x; ac2.y += q2 * v2.y;
            }
        }

        #pragma unroll
        for (int o = 16; o > 0; o >>= 1) {
            d0 += __shfl_xor_sync(0xffffffffu, d0, o);
            d1 += __shfl_xor_sync(0xffffffffu, d1, o);
            d2 += __shfl_xor_sync(0xffffffffu, d2, o);
        }
        const float i0 = 1.f / d0, i1 = 1.f / d1, i2 = 1.f / d2;

        const float2* b2 = reinterpret_cast<const float2*>(bias);
        float2* sp = reinterpret_cast<float2*>(smax[wid]);
        float2 bb, vv;
        bb = b2[lane];
        vv.x = ac0.x * i0 + bb.x; vv.x = (vv.x > 0.f) ? vv.x : 0.01f * vv.x;
        vv.y = ac0.y * i0 + bb.y; vv.y = (vv.y > 0.f) ? vv.y : 0.01f * vv.y;
        sp[lane] = vv;
        bb = b2[lane + 32];
        vv.x = ac1.x * i1 + bb.x; vv.x = (vv.x > 0.f) ? vv.x : 0.01f * vv.x;
        vv.y = ac1.y * i1 + bb.y; vv.y = (vv.y > 0.f) ? vv.y : 0.01f * vv.y;
        sp[lane + 32] = vv;
        bb = b2[lane + 64];
        vv.x = ac2.x * i2 + bb.x; vv.x = (vv.x > 0.f) ? vv.x : 0.01f * vv.x;
        vv.y = ac2.y * i2 + bb.y; vv.y = (vv.y > 0.f) ? vv.y : 0.01f * vv.y;
        sp[lane + 64] = vv;
        if (lane == 0) sbatch[wid] = batch[n];
    } else {
        if (lane == 0) sbatch[wid] = -1;
    }
    __syncthreads();

    // per-column run-wise max over the block's 8 nodes, then atomicMax
    if (threadIdx.x < HIDDEN) {
        const int col = threadIdx.x;
        float cur = -INFINITY;
        int curg = -2;
        #pragma unroll
        for (int w = 0; w < 8; w++) {
            int g = sbatch[w];
            if (g < 0) continue;
            if (g != curg) {
                if (curg >= 0)
                    atomicMax(&g_pooled_u[curg * HIDDEN + col], fenc(cur));
                curg = g;
                cur = -INFINITY;
            }
            cur = fmaxf(cur, smax[w][col]);
        }
        if (curg >= 0)
            atomicMax(&g_pooled_u[curg * HIDDEN + col], fenc(cur));
    }
}

// ---------------- 4) classifier (warp per output) ----------------------------
__global__ void __launch_bounds__(256) cls_kernel(const float* __restrict__ cw,
                                                  const float* __restrict__ cb,
                                                  float* __restrict__ out) {
    const int w = (blockIdx.x * 256 + threadIdx.x) >> 5;   // 0..255
    const int lane = threadIdx.x & 31;
    if (w >= NUM_GRAPHS * NUM_CLASSES) return;
    const int g = w >> 1, c = w & 1;
    float s = 0.f;
    #pragma unroll
    for (int i = 0; i < HIDDEN / 32; i++) {
        int k = lane + 32 * i;
        s += fdec(g_pooled_u[g * HIDDEN + k]) * cw[k * NUM_CLASSES + c];
    }
    #pragma unroll
    for (int o = 16; o > 0; o >>= 1)
        s += __shfl_xor_sync(0xffffffffu, s, o);
    if (lane == 0) out[g * NUM_CLASSES + c] = s + cb[c];
}

// ---------------- launch: fork CSR+sort chain onto a side stream -------------
extern "C" void kernel_launch(void* const* d_in, const int* in_sizes, int n_in,
                              void* d_out, int out_size) {
    const float* x     = (const float*)d_in[0];
    const int*   ei    = (const int*)d_in[1];
    const int*   batch = (const int*)d_in[2];
    const float* W     = (const float*)d_in[3];
    const float* att_s = (const float*)d_in[4];
    const float* att_d = (const float*)d_in[5];
    const float* bias  = (const float*)d_in[6];
    const float* cw    = (const float*)d_in[7];
    const float* cb    = (const float*)d_in[8];
    float* out = (float*)d_out;

    cudaStream_t s2;
    cudaStreamCreateWithFlags(&s2, cudaStreamNonBlocking);
    cudaEvent_t evFork, evJoin;
    cudaEventCreateWithFlags(&evFork, cudaEventDisableTiming);
    cudaEventCreateWithFlags(&evJoin, cudaEventDisableTiming);

    cudaEventRecord(evFork, 0);
    cudaStreamWaitEvent(s2, evFork, 0);

    // side stream: CSR build + degree-bucketed permutation
    count_kernel<<<(N_EDGES + 255) / 256, 256, 0, s2>>>(ei);
    scan1_kernel<<<SCAN_NB, SCAN_BLK, 0, s2>>>();
    scan2_kernel<<<1, 128, 0, s2>>>();
    scan3_kernel<<<SCAN_NB, SCAN_BLK, 0, s2>>>();
    sort_hist_kernel<<<(N_NODES + 255) / 256, 256, 0, s2>>>(batch);
    sort_scan_kernel<<<1, SCAN_BLK, 0, s2>>>();
    sort_scatter_kernel<<<(N_NODES + 255) / 256, 256, 0, s2>>>(batch);
    fill_kernel<<<(N_EDGES + 255) / 256, 256, 0, s2>>>(ei);
    cudaEventRecord(evJoin, s2);

    // main stream: GEMM runs concurrently with the CSR chain
    gemm_att_kernel<<<1480, 192>>>(x, W, att_s, att_d);

    // join, then aggregation + classifier on the main stream
    cudaStreamWaitEvent(0, evJoin, 0);
    agg_kernel<<<(N_NODES + 7) / 8, 256>>>(bias, batch);
    cls_kernel<<<32, 256>>>(cw, cb, out);

    cudaEventDestroy(evFork);
    cudaEventDestroy(evJoin);
    cudaStreamDestroy(s2);
}